// round 3
// baseline (speedup 1.0000x reference)
#include <cuda_runtime.h>
#include <math.h>

// Problem constants
#define NBc   16
#define NAc   5
#define NKc   9
#define NCc   13
#define NHc   38
#define NWc   38
#define MAXTc 50
#define NPIX  (NHc*NWc)        // 1444
#define NANCH (NAc*NPIX)       // 7220
#define NTOTc (NBc*NANCH)      // 115520
#define CHPA  (2*NKc+1+NCc)    // 32 channels per anchor
#define TROW  21               // floats per target row

#define TPB   128
#define BPB   ((NANCH + TPB - 1)/TPB)  // 57 blocks per batch
#define NBLK  (NBc*BPB)                // 912 blocks total

#define SCX   (640.0f/38.0f)
#define SCY   (480.0f/38.0f)

// corner-conf: c = (exp(2*(1 - d/80)) - 1)/(e^2 - 1), mean over 9 corners.
// carry s = sum_k(exp(...)-1); conf = s / (9*(e^2-1)).
#define DENOM9   57.50150489f
#define STHRESH  34.50090293f   // 0.6 * 9 * (e^2 - 1)

__device__ float g_part[NBLK][2];   // (baseLoss, confLoss) partials
__device__ int   g_cnt = 0;

__device__ __forceinline__ float sigf(float x) { return 1.0f / (1.0f + __expf(-x)); }

__global__ void __launch_bounds__(TPB)
k_main(const float* __restrict__ out,
       const float* __restrict__ tgt,
       const float* __restrict__ anc,
       const void*  __restrict__ epoch_ptr,
       float* __restrict__ d_out) {
    __shared__ float  s_t[MAXTc*TROW];       // raw target rows
    __shared__ int    s_nv;
    __shared__ int    s_key[MAXTc];          // (best<<12)|(gj<<6)|gi
    __shared__ float  s_tconf[MAXTc], s_cls[MAXTc];
    __shared__ float2 s_g [MAXTc*NKc];       // corner (gx,gy) in pixels
    __shared__ float2 s_v [MAXTc*NKc];       // coord targets (vx,vy)
    __shared__ float  red[TPB][2];

    const int b    = blockIdx.x / BPB;
    const int cell = (blockIdx.x % BPB) * TPB + threadIdx.x;
    const bool ok  = (cell < NANCH);

    // ---------- issue per-cell global loads EARLY (overlap with meta) ------
    int a = 0, pix = 0, h = 0, w = 0;
    const float* baseo = out;
    float rawx[NKc], rawy[NKc], rawc = 0.0f;
    if (ok) {
        a   = cell / NPIX;
        pix = cell % NPIX;
        h = pix / NWc; w = pix % NWc;
        baseo = out + ((size_t)(b * NAc + a) * CHPA) * NPIX + pix;
        #pragma unroll
        for (int k = 0; k < NKc; ++k) {
            rawx[k] = baseo[(2*k)   * NPIX];
            rawy[k] = baseo[(2*k+1) * NPIX];
        }
        rawc = baseo[(2*NKc) * NPIX];
    }

    // ---------- load targets to shared (coalesced) -------------------------
    for (int i = threadIdx.x; i < MAXTc*TROW; i += TPB)
        s_t[i] = tgt[(size_t)b * (MAXTc*TROW) + i];
    __syncthreads();

    // ---------- validity prefix (early-break scan, expected ~5 iters) ------
    if (threadIdx.x == 0) {
        int nv = 0;
        while (nv < MAXTc && s_t[nv*TROW + 1] != 0.0f) nv++;
        s_nv = nv;
    }
    __syncthreads();
    const int nv = s_nv;

    // ---------- per-target meta ------------------------------------------
    if (threadIdx.x < nv) {
        const int t = threadIdx.x;
        const float* tb = &s_t[t*TROW];

        // best anchor by IoU (first-max)
        float gw = tb[19] * (float)NWc;
        float gh = tb[20] * (float)NHc;
        float best = -1.0f; int bn = 0;
        #pragma unroll
        for (int aa = 0; aa < NAc; ++aa) {
            float aw = anc[2*aa], ah = anc[2*aa+1];
            float cw = fminf(gw, aw), ch = fminf(gh, ah);
            float iou = 0.0f;
            if (cw > 0.0f && ch > 0.0f) {
                float ca = cw * ch;
                iou = ca / (gw * gh + aw * ah - ca);
            }
            if (iou > best) { best = iou; bn = aa; }
        }
        int gi0 = (int)floorf(tb[1] * (float)NWc);
        int gj0 = (int)floorf(tb[2] * (float)NHc);
        s_key[t] = (bn << 12) | (gj0 << 6) | gi0;
        s_cls[t] = tb[0];

        #pragma unroll
        for (int k = 0; k < NKc; ++k) {
            float gx = tb[1 + 2*k], gy = tb[2 + 2*k];
            s_g[t*NKc + k] = make_float2(gx * 640.0f, gy * 480.0f);
            s_v[t*NKc + k] = make_float2(gx * (float)NWc - (float)gi0,
                                         gy * (float)NHc - (float)gj0);
        }

        // tconf at the pidx-shifted cell
        long long p = (long long)b * NANCH - NPIX + (long long)gj0 * NWc + gi0;
        const long long tot = NTOTc;
        p = ((p % tot) + tot) % tot;
        int b2  = (int)(p / NANCH);
        int rem = (int)(p % NANCH);
        int a2  = rem / NPIX;
        int px2 = rem % NPIX;
        int h2 = px2 / NWc, w2 = px2 % NWc;
        const float* bo2 = out + ((size_t)(b2 * NAc + a2) * CHPA) * NPIX + px2;

        float s = 0.0f;
        #pragma unroll
        for (int k = 0; k < NKc; ++k) {
            float xv = bo2[(2*k)   * NPIX];
            float yv = bo2[(2*k+1) * NPIX];
            if (k == 0) { xv = sigf(xv); yv = sigf(yv); }
            float Px = (xv + (float)w2) * SCX;
            float Py = (yv + (float)h2) * SCY;
            float dx = s_g[t*NKc + k].x - Px;
            float dy = s_g[t*NKc + k].y - Py;
            float d2 = fmaf(dx, dx, dy * dy);
            if (d2 < 6400.0f) s += __expf(2.0f - sqrtf(d2) * 0.025f) - 1.0f;
        }
        s_tconf[t] = s * (1.0f / DENOM9);
    }
    __syncthreads();

    // ---------- per-cell loss ---------------------------------------------
    float baseLoss = 0.0f, confLoss = 0.0f;

    if (ok) {
        rawx[0] = sigf(rawx[0]);
        rawy[0] = sigf(rawy[0]);
        float Px[NKc], Py[NKc];
        #pragma unroll
        for (int k = 0; k < NKc; ++k) {
            Px[k] = (rawx[k] + (float)w) * SCX;
            Py[k] = (rawy[k] + (float)h) * SCY;
        }
        float confv = sigf(rawc);

        // match detection (last-write-wins)
        const int mykey = (a << 12) | (h << 6) | w;
        int m = -1;
        for (int t = 0; t < nv; ++t)
            if (s_key[t] == mykey) m = t;

        if (m >= 0) {
            // coord loss
            #pragma unroll
            for (int k = 0; k < NKc; ++k) {
                float2 v = s_v[m*NKc + k];
                float dx = rawx[k] - v.x;
                float dy = rawy[k] - v.y;
                baseLoss += 0.5f * (dx*dx + dy*dy);
            }
            // class CE (rare path — load logits now)
            float l[NCc]; float mx = -1e30f;
            #pragma unroll
            for (int c = 0; c < NCc; ++c) {
                l[c] = baseo[(2*NKc + 1 + c) * NPIX];
                mx = fmaxf(mx, l[c]);
            }
            float se = 0.0f;
            #pragma unroll
            for (int c = 0; c < NCc; ++c) se += __expf(l[c] - mx);
            int lab = (int)s_cls[m];
            lab = lab < 0 ? 0 : (lab > NCc - 1 ? NCc - 1 : lab);
            baseLoss += __logf(se) + mx - l[lab];
            float dc = confv - s_tconf[m];
            confLoss = 2.5f * dc * dc;
        } else {
            // silence check: exists t with corner-sum > threshold?
            bool silent = false;
            for (int t = 0; t < nv; ++t) {
                float d2[NKc];
                #pragma unroll
                for (int k = 0; k < NKc; ++k) {
                    float2 g = s_g[t*NKc + k];
                    float dx = Px[k] - g.x;
                    float dy = Py[k] - g.y;
                    d2[k] = fmaf(dx, dx, dy * dy);
                }
                // fmin tree
                float m01 = fminf(d2[0], d2[1]), m23 = fminf(d2[2], d2[3]);
                float m45 = fminf(d2[4], d2[5]), m67 = fminf(d2[6], d2[7]);
                float dmin = fminf(fminf(fminf(m01, m23), fminf(m45, m67)), d2[8]);
                if (dmin < 6400.0f) {
                    float ssum = 0.0f;
                    #pragma unroll
                    for (int k = 0; k < NKc; ++k)
                        if (d2[k] < 6400.0f)
                            ssum += __expf(2.0f - sqrtf(d2[k]) * 0.025f) - 1.0f;
                    if (ssum > STHRESH) { silent = true; break; }
                }
            }
            if (!silent) confLoss = 0.5f * confv * confv;
        }
    }

    // ---------- deterministic block reduction -----------------------------
    red[threadIdx.x][0] = baseLoss;
    red[threadIdx.x][1] = confLoss;
    __syncthreads();
    for (int s = TPB/2; s > 0; s >>= 1) {
        if (threadIdx.x < s) {
            red[threadIdx.x][0] += red[threadIdx.x + s][0];
            red[threadIdx.x][1] += red[threadIdx.x + s][1];
        }
        __syncthreads();
    }
    if (threadIdx.x == 0) {
        g_part[blockIdx.x][0] = red[0][0];
        g_part[blockIdx.x][1] = red[0][1];
    }

    // ---------- last-block-done final reduction ---------------------------
    __shared__ bool s_last;
    __threadfence();
    if (threadIdx.x == 0) {
        int old = atomicAdd(&g_cnt, 1);
        s_last = (old == NBLK - 1);
    }
    __syncthreads();
    if (!s_last) return;

    float rb = 0.0f, rc = 0.0f;
    #pragma unroll
    for (int j = 0; j < (NBLK + TPB - 1)/TPB; ++j) {
        int idx = threadIdx.x + j * TPB;
        if (idx < NBLK) { rb += g_part[idx][0]; rc += g_part[idx][1]; }
    }
    red[threadIdx.x][0] = rb;
    red[threadIdx.x][1] = rc;
    __syncthreads();
    for (int s = TPB/2; s > 0; s >>= 1) {
        if (threadIdx.x < s) {
            red[threadIdx.x][0] += red[threadIdx.x + s][0];
            red[threadIdx.x][1] += red[threadIdx.x + s][1];
        }
        __syncthreads();
    }
    if (threadIdx.x == 0) {
        int ev = ((const int*)epoch_ptr)[0];
        if (ev > 1000000 || ev < -1000000) ev = (int)__int_as_float(ev);
        float total = red[0][0];
        if (ev > 15) total += red[0][1];
        d_out[0] = total;
        g_cnt = 0;   // reset for graph replay
    }
}

extern "C" void kernel_launch(void* const* d_in, const int* in_sizes, int n_in,
                              void* d_out, int out_size) {
    const float* out_t = (const float*)d_in[0];
    const float* tgt   = (const float*)d_in[1];
    const float* anc   = (const float*)d_in[2];
    const void*  epoch = d_in[3];
    k_main<<<NBLK, TPB>>>(out_t, tgt, anc, epoch, (float*)d_out);
}

// round 4
// speedup vs baseline: 1.0274x; 1.0274x over previous
#include <cuda_runtime.h>
#include <math.h>

// Problem constants
#define NBc   16
#define NAc   5
#define NKc   9
#define NCc   13
#define NHc   38
#define NWc   38
#define MAXTc 50
#define NPIX  (NHc*NWc)        // 1444
#define NANCH (NAc*NPIX)       // 7220
#define NTOTc (NBc*NANCH)      // 115520
#define CHPA  (2*NKc+1+NCc)    // 32 channels per anchor
#define TROW  21

#define TPB   128
#define BPB   ((NANCH + TPB - 1)/TPB)  // 57 blocks per batch
#define NBLK  (NBc*BPB)                // 912 blocks

#define SCX   (640.0f/38.0f)
#define SCY   (480.0f/38.0f)

#define DENOM9   57.50150489f
#define STHRESH  34.50090293f   // 0.6 * 9 * (e^2 - 1)

__device__ float g_part[NBLK][2];
__device__ int   g_cnt = 0;

__device__ __forceinline__ float sigf(float x) { return 1.0f / (1.0f + __expf(-x)); }

__global__ void __launch_bounds__(TPB, 6)
k_main(const float* __restrict__ out,
       const float* __restrict__ tgt,
       const float* __restrict__ anc,
       const void*  __restrict__ epoch_ptr,
       float* __restrict__ d_out) {
    __shared__ float  s_t[MAXTc*TROW];
    __shared__ int    s_nv;
    __shared__ int    s_key[MAXTc];          // (best<<12)|(gj<<6)|gi
    __shared__ float  s_tconf[MAXTc], s_cls[MAXTc];
    __shared__ float2 s_g [MAXTc*NKc];       // corner (gx,gy) pixels
    __shared__ float2 s_v [MAXTc*NKc];       // coord targets
    __shared__ float2 s_wred[TPB/32];

    const int tid  = threadIdx.x;
    const int lane = tid & 31;
    const int wid  = tid >> 5;
    const int b    = blockIdx.x / BPB;
    const int cell = (blockIdx.x % BPB) * TPB + tid;
    const bool ok  = (cell < NANCH);

    // ---- per-cell loads, issued early; fold into Px/Py immediately -------
    int a = 0, h = 0, w = 0;
    const float* baseo = out;
    float Px[NKc], Py[NKc], confv = 0.0f;
    if (ok) {
        a = cell / NPIX;
        int pix = cell % NPIX;
        h = pix / NWc; w = pix % NWc;
        baseo = out + ((size_t)(b * NAc + a) * CHPA) * NPIX + pix;
        float rc = baseo[(2*NKc) * NPIX];
        #pragma unroll
        for (int k = 0; k < NKc; ++k) {
            float xv = baseo[(2*k)   * NPIX];
            float yv = baseo[(2*k+1) * NPIX];
            if (k == 0) { xv = sigf(xv); yv = sigf(yv); }
            Px[k] = (xv + (float)w) * SCX;
            Py[k] = (yv + (float)h) * SCY;
        }
        confv = sigf(rc);
    }

    // ---- targets -> shared (coalesced) ------------------------------------
    for (int i = tid; i < MAXTc*TROW; i += TPB)
        s_t[i] = tgt[(size_t)b * (MAXTc*TROW) + i];
    __syncthreads();

    // ---- validity prefix via ballots (warp 0) ------------------------------
    if (wid == 0) {
        unsigned m0 = __ballot_sync(0xFFFFFFFFu, s_t[lane*TROW + 1] != 0.0f);
        unsigned m1 = __ballot_sync(0xFFFFFFFFu,
                          (lane < MAXTc - 32) && (s_t[(lane+32)*TROW + 1] != 0.0f));
        if (lane == 0) {
            int nv;
            if (~m0) nv = __ffs(~m0) - 1;
            else {
                unsigned inv = (~m1) & ((1u << (MAXTc - 32)) - 1u);
                nv = inv ? 32 + __ffs(inv) - 1 : MAXTc;
            }
            s_nv = nv;
        }
    }
    __syncthreads();
    const int nv = s_nv;

    // ---- per-target meta ---------------------------------------------------
    if (tid < nv) {
        const int t = tid;
        const float* tb = &s_t[t*TROW];

        float gw = tb[19] * (float)NWc;
        float gh = tb[20] * (float)NHc;
        float best = -1.0f; int bn = 0;
        #pragma unroll
        for (int aa = 0; aa < NAc; ++aa) {
            float aw = anc[2*aa], ah = anc[2*aa+1];
            float cw = fminf(gw, aw), ch = fminf(gh, ah);
            float iou = 0.0f;
            if (cw > 0.0f && ch > 0.0f) {
                float ca = cw * ch;
                iou = ca / (gw * gh + aw * ah - ca);
            }
            if (iou > best) { best = iou; bn = aa; }
        }
        int gi0 = (int)floorf(tb[1] * (float)NWc);
        int gj0 = (int)floorf(tb[2] * (float)NHc);
        s_key[t] = (bn << 12) | (gj0 << 6) | gi0;
        s_cls[t] = tb[0];

        #pragma unroll
        for (int k = 0; k < NKc; ++k) {
            float gx = tb[1 + 2*k], gy = tb[2 + 2*k];
            s_g[t*NKc + k] = make_float2(gx * 640.0f, gy * 480.0f);
            s_v[t*NKc + k] = make_float2(gx * (float)NWc - (float)gi0,
                                         gy * (float)NHc - (float)gj0);
        }

        long long p = (long long)b * NANCH - NPIX + (long long)gj0 * NWc + gi0;
        const long long tot = NTOTc;
        p = ((p % tot) + tot) % tot;
        int b2  = (int)(p / NANCH);
        int rem = (int)(p % NANCH);
        int a2  = rem / NPIX;
        int px2 = rem % NPIX;
        int h2 = px2 / NWc, w2 = px2 % NWc;
        const float* bo2 = out + ((size_t)(b2 * NAc + a2) * CHPA) * NPIX + px2;

        float s = 0.0f;
        #pragma unroll
        for (int k = 0; k < NKc; ++k) {
            float xv = bo2[(2*k)   * NPIX];
            float yv = bo2[(2*k+1) * NPIX];
            if (k == 0) { xv = sigf(xv); yv = sigf(yv); }
            float qx = (xv + (float)w2) * SCX;
            float qy = (yv + (float)h2) * SCY;
            float dx = s_g[t*NKc + k].x - qx;
            float dy = s_g[t*NKc + k].y - qy;
            float d2 = fmaf(dx, dx, dy * dy);
            if (d2 < 6400.0f) s += __expf(2.0f - sqrtf(d2) * 0.025f) - 1.0f;
        }
        s_tconf[t] = s * (1.0f / DENOM9);
    }
    __syncthreads();

    // ---- per-cell loss ------------------------------------------------------
    float baseLoss = 0.0f, confLoss = 0.0f;

    if (ok) {
        const int mykey = (a << 12) | (h << 6) | w;
        int m = -1;
        for (int t = 0; t < nv; ++t)
            if (s_key[t] == mykey) m = t;

        if (m >= 0) {
            // rare path: reload raw channel values (L1 hits) for coord loss
            #pragma unroll
            for (int k = 0; k < NKc; ++k) {
                float xv = baseo[(2*k)   * NPIX];
                float yv = baseo[(2*k+1) * NPIX];
                if (k == 0) { xv = sigf(xv); yv = sigf(yv); }
                float2 v = s_v[m*NKc + k];
                float dx = xv - v.x;
                float dy = yv - v.y;
                baseLoss += 0.5f * (dx*dx + dy*dy);
            }
            // class CE
            float l[NCc]; float mx = -1e30f;
            #pragma unroll
            for (int c = 0; c < NCc; ++c) {
                l[c] = baseo[(2*NKc + 1 + c) * NPIX];
                mx = fmaxf(mx, l[c]);
            }
            float se = 0.0f;
            #pragma unroll
            for (int c = 0; c < NCc; ++c) se += __expf(l[c] - mx);
            int lab = (int)s_cls[m];
            lab = lab < 0 ? 0 : (lab > NCc - 1 ? NCc - 1 : lab);
            baseLoss += __logf(se) + mx - l[lab];
            float dc = confv - s_tconf[m];
            confLoss = 2.5f * dc * dc;
        } else {
            bool silent = false;
            #pragma unroll 2
            for (int t = 0; t < nv; ++t) {
                float d2[NKc];
                #pragma unroll
                for (int k = 0; k < NKc; ++k) {
                    float2 g = s_g[t*NKc + k];
                    float dx = Px[k] - g.x;
                    float dy = Py[k] - g.y;
                    d2[k] = fmaf(dx, dx, dy * dy);
                }
                float m01 = fminf(d2[0], d2[1]), m23 = fminf(d2[2], d2[3]);
                float m45 = fminf(d2[4], d2[5]), m67 = fminf(d2[6], d2[7]);
                float dmin = fminf(fminf(fminf(m01, m23), fminf(m45, m67)), d2[8]);
                if (dmin < 6400.0f) {
                    float ssum = 0.0f;
                    #pragma unroll
                    for (int k = 0; k < NKc; ++k)
                        if (d2[k] < 6400.0f)
                            ssum += __expf(2.0f - sqrtf(d2[k]) * 0.025f) - 1.0f;
                    if (ssum > STHRESH) { silent = true; break; }
                }
            }
            if (!silent) confLoss = 0.5f * confv * confv;
        }
    }

    // ---- block reduction: warp shuffles + 4-way fixed-order combine --------
    float v0 = baseLoss, v1 = confLoss;
    #pragma unroll
    for (int o = 16; o > 0; o >>= 1) {
        v0 += __shfl_down_sync(0xFFFFFFFFu, v0, o);
        v1 += __shfl_down_sync(0xFFFFFFFFu, v1, o);
    }
    if (lane == 0) s_wred[wid] = make_float2(v0, v1);
    __syncthreads();
    if (tid == 0) {
        float rb = s_wred[0].x + s_wred[1].x + s_wred[2].x + s_wred[3].x;
        float rc = s_wred[0].y + s_wred[1].y + s_wred[2].y + s_wred[3].y;
        g_part[blockIdx.x][0] = rb;
        g_part[blockIdx.x][1] = rc;
    }

    // ---- last-block-done final reduction ------------------------------------
    __shared__ bool s_last;
    __threadfence();
    if (tid == 0) {
        int old = atomicAdd(&g_cnt, 1);
        s_last = (old == NBLK - 1);
    }
    __syncthreads();
    if (!s_last) return;

    float rb = 0.0f, rc = 0.0f;
    #pragma unroll
    for (int j = 0; j < (NBLK + TPB - 1)/TPB; ++j) {
        int idx = tid + j * TPB;
        if (idx < NBLK) { rb += g_part[idx][0]; rc += g_part[idx][1]; }
    }
    #pragma unroll
    for (int o = 16; o > 0; o >>= 1) {
        rb += __shfl_down_sync(0xFFFFFFFFu, rb, o);
        rc += __shfl_down_sync(0xFFFFFFFFu, rc, o);
    }
    if (lane == 0) s_wred[wid] = make_float2(rb, rc);
    __syncthreads();
    if (tid == 0) {
        float tb2 = s_wred[0].x + s_wred[1].x + s_wred[2].x + s_wred[3].x;
        float tc2 = s_wred[0].y + s_wred[1].y + s_wred[2].y + s_wred[3].y;
        int ev = ((const int*)epoch_ptr)[0];
        if (ev > 1000000 || ev < -1000000) ev = (int)__int_as_float(ev);
        float total = tb2;
        if (ev > 15) total += tc2;
        d_out[0] = total;
        g_cnt = 0;   // reset for graph replay
    }
}

extern "C" void kernel_launch(void* const* d_in, const int* in_sizes, int n_in,
                              void* d_out, int out_size) {
    const float* out_t = (const float*)d_in[0];
    const float* tgt   = (const float*)d_in[1];
    const float* anc   = (const float*)d_in[2];
    const void*  epoch = d_in[3];
    k_main<<<NBLK, TPB>>>(out_t, tgt, anc, epoch, (float*)d_out);
}